// round 12
// baseline (speedup 1.0000x reference)
#include <cuda_runtime.h>
#include <cuda_bf16.h>

// Problem constants
#define N_WORKER   1807
#define N_PROJECT  2490
#define EMB        10
#define STATE_DIM  20
#define HIDDEN     40
#define NCAND      2489        // candidates = project_emb rows 1..2489 (cand c -> row c+1)
#define BATCH      65536

#define NSPLIT     13
#define SPLIT_CAND 192         // 13*192 = 2496 >= 2489, NaN pad
#define THREADS    128
#define SPT        4           // samples per thread in actor
#define SBLK       (BATCH / (THREADS * SPT))   // 128 sample blocks
#define ACTOR_CTAS (SBLK * NSPLIT)             // 1664 CTAs @4/SM resident

#define W2T_PITCH  12          // padded transposed-W2 row (48B, 16-aligned)

// per-sample action weights (plain floats; actor packs sample-pairs)
__device__ float g_w[BATCH][EMB];
// per-sample packed partials, row-contiguous: [sample][split] (pad 16 -> 128B rows)
__device__ __align__(16) unsigned long long g_pack[BATCH][16];

// ---- packed f32x2 helpers (sm_103a FFMA2 path) ----
__device__ __forceinline__ unsigned long long pack2(float lo, float hi) {
    unsigned long long r;
    asm("mov.b64 %0, {%1, %2};" : "=l"(r) : "f"(lo), "f"(hi));
    return r;
}
__device__ __forceinline__ void unpack2(unsigned long long v, float& lo, float& hi) {
    asm("mov.b64 {%0, %1}, %2;" : "=f"(lo), "=f"(hi) : "l"(v));
}
__device__ __forceinline__ unsigned long long fmul2(unsigned long long a, unsigned long long b) {
    unsigned long long d;
    asm("mul.rn.f32x2 %0, %1, %2;" : "=l"(d) : "l"(a), "l"(b));
    return d;
}
__device__ __forceinline__ unsigned long long ffma2(unsigned long long a, unsigned long long b,
                                                    unsigned long long c) {
    unsigned long long d;
    asm("fma.rn.f32x2 %0, %1, %2, %3;" : "=l"(d) : "l"(a), "l"(b), "l"(c));
    return d;
}

__device__ __forceinline__ int load_id(const void* p, int i, int ids64) {
    return ids64 ? (int)((const long long*)p)[i] : ((const int*)p)[i];
}

// ---- MLP kernel (detect fused): one sample per thread, vectorized LDS ----
__global__ __launch_bounds__(THREADS)
void mlp_kernel(const void* __restrict__ idA,
                const void* __restrict__ idB,
                const float* __restrict__ worker_emb,
                const float* __restrict__ project_emb,
                const float* __restrict__ W1,
                const float* __restrict__ b1,
                const float* __restrict__ W2,
                const float* __restrict__ b2)
{
    __shared__ __align__(16) float sW1[HIDDEN * STATE_DIM];   // [k][j], 80B rows
    __shared__ __align__(16) float sW2t[HIDDEN * W2T_PITCH];  // [k][d], 48B rows
    __shared__ float sb1[HIDDEN];
    __shared__ float sb2[EMB];
    __shared__ unsigned int s_or[4], s_mx[4];
    __shared__ int s_swap, s_ids64;

    const int tid = threadIdx.x;

    // -- fused id-layout detection (128 sampled u64-slots; P[err] < e^-41) --
    {
        const unsigned int* a32 = (const unsigned int*)idA;
        const unsigned int* b32 = (const unsigned int*)idB;
        const int i = tid * (BATCH / 256);
        unsigned int odd_or  = a32[2 * i + 1] | b32[2 * i + 1];
        unsigned int even_mx = a32[2 * i];
        #pragma unroll
        for (int o = 16; o > 0; o >>= 1) {
            odd_or  |= __shfl_xor_sync(0xffffffffu, odd_or, o);
            even_mx  = max(even_mx, __shfl_xor_sync(0xffffffffu, even_mx, o));
        }
        if ((tid & 31) == 0) { s_or[tid >> 5] = odd_or; s_mx[tid >> 5] = even_mx; }
    }

    for (int i = tid; i < HIDDEN * STATE_DIM; i += THREADS) sW1[i] = W1[i];
    // transpose W2 into padded [k][d] layout
    for (int i = tid; i < HIDDEN * EMB; i += THREADS) {
        const int d = i / HIDDEN;
        const int k = i - d * HIDDEN;
        sW2t[k * W2T_PITCH + d] = W2[i];
    }
    if (tid < HIDDEN) sb1[tid] = b1[tid];
    if (tid < EMB)    sb2[tid] = b2[tid];
    __syncthreads();

    if (tid == 0) {
        unsigned int oo = 0, mm = 0;
        #pragma unroll
        for (int w = 0; w < 4; w++) { oo |= s_or[w]; mm = max(mm, s_mx[w]); }
        s_ids64 = (oo == 0) ? 1 : 0;
        s_swap  = (mm >= (unsigned)N_WORKER) ? 1 : 0;
    }
    __syncthreads();

    const int swap  = s_swap;
    const int ids64 = s_ids64;
    const void* worker_ids  = swap ? idB : idA;
    const void* project_ids = swap ? idA : idB;

    const int g  = blockIdx.x * THREADS + tid;
    const int wi = load_id(worker_ids,  g, ids64);
    const int pi = load_id(project_ids, g, ids64);

    // vector gathers: row = 10 floats -> 5x float2 (8-aligned)
    float x[STATE_DIM];
    {
        const float2* wrow = reinterpret_cast<const float2*>(worker_emb + wi * EMB);
        const float2* prow = reinterpret_cast<const float2*>(project_emb + pi * EMB);
        #pragma unroll
        for (int j = 0; j < 5; j++) {
            const float2 a = __ldg(wrow + j);
            x[2 * j] = a.x; x[2 * j + 1] = a.y;
        }
        #pragma unroll
        for (int j = 0; j < 5; j++) {
            const float2 b = __ldg(prow + j);
            x[EMB + 2 * j] = b.x; x[EMB + 2 * j + 1] = b.y;
        }
    }

    float a[EMB];
    #pragma unroll
    for (int d = 0; d < EMB; d++) a[d] = sb2[d];

    // hidden units 2 at a time; all weight LDS are 128-bit
    #pragma unroll 4
    for (int k0 = 0; k0 < HIDDEN; k0 += 2) {
        const float4* r0 = reinterpret_cast<const float4*>(sW1 + k0 * STATE_DIM);
        const float4* r1 = reinterpret_cast<const float4*>(sW1 + (k0 + 1) * STATE_DIM);
        float h0 = sb1[k0], h1 = sb1[k0 + 1];
        #pragma unroll
        for (int q4 = 0; q4 < 5; q4++) {
            const float4 w0 = r0[q4];
            const float4 w1 = r1[q4];
            const int j = q4 * 4;
            h0 += w0.x * x[j] + w0.y * x[j + 1] + w0.z * x[j + 2] + w0.w * x[j + 3];
            h1 += w1.x * x[j] + w1.y * x[j + 1] + w1.z * x[j + 2] + w1.w * x[j + 3];
        }
        h0 = fmaxf(h0, 0.0f);
        h1 = fmaxf(h1, 0.0f);

        const float4* c0 = reinterpret_cast<const float4*>(sW2t + k0 * W2T_PITCH);
        const float4* c1 = reinterpret_cast<const float4*>(sW2t + (k0 + 1) * W2T_PITCH);
        const float4 u0 = c0[0], u1 = c0[1], u2 = c0[2];
        const float4 v0 = c1[0], v1 = c1[1], v2 = c1[2];
        a[0] += u0.x * h0 + v0.x * h1;
        a[1] += u0.y * h0 + v0.y * h1;
        a[2] += u0.z * h0 + v0.z * h1;
        a[3] += u0.w * h0 + v0.w * h1;
        a[4] += u1.x * h0 + v1.x * h1;
        a[5] += u1.y * h0 + v1.y * h1;
        a[6] += u1.z * h0 + v1.z * h1;
        a[7] += u1.w * h0 + v1.w * h1;
        a[8] += u2.x * h0 + v2.x * h1;
        a[9] += u2.y * h0 + v2.y * h1;
    }

    // g_w row is 40B -> 8-byte aligned: 5 STG.64
    float2* wrow_out = reinterpret_cast<float2*>(g_w[g]);
    #pragma unroll
    for (int j = 0; j < 5; j++) wrow_out[j] = make_float2(a[2 * j], a[2 * j + 1]);
}

// ---- actor: sample-pair packed dots; 4 samples/thread; 16 warps/SM ----
__global__ __launch_bounds__(THREADS, 4)
void actor_kernel(const float* __restrict__ project_emb)
{
    // duplicated-pair table: tbl[c*10 + j] = (t_c[j], t_c[j]); 15360 B
    __shared__ __align__(16) unsigned long long tbl[SPLIT_CAND * EMB];

    const int split = blockIdx.x % NSPLIT;
    const int sblk  = blockIdx.x / NSPLIT;
    const int c0    = split * SPLIT_CAND;     // global candidate base
    const int tid   = threadIdx.x;

    // stage duplicated pairs; NaN pad beyond NCAND (NaN never wins '>')
    for (int e = tid; e < SPLIT_CAND * EMB; e += THREADS) {
        const int c = e / EMB;
        const int j = e - c * EMB;
        const int ci = c0 + c;
        const float t = (ci < NCAND) ? __ldg(project_emb + (ci + 1) * EMB + j)
                                     : __int_as_float(0x7fffffff);
        tbl[e] = pack2(t, t);
    }

    // per-thread: 4 samples -> 2 sample-pair packed weight vectors (40 regs)
    int g[SPT];
    unsigned long long wd01[EMB], wd23[EMB];
    {
        float aw[SPT][EMB];
        #pragma unroll
        for (int s = 0; s < SPT; s++) {
            g[s] = (sblk * SPT + s) * THREADS + tid;
            const float2* wr = reinterpret_cast<const float2*>(g_w[g[s]]);
            #pragma unroll
            for (int j = 0; j < 5; j++) {
                const float2 v = __ldg(wr + j);
                aw[s][2 * j] = v.x; aw[s][2 * j + 1] = v.y;
            }
        }
        #pragma unroll
        for (int j = 0; j < EMB; j++) {
            wd01[j] = pack2(aw[0][j], aw[1][j]);
            wd23[j] = pack2(aw[2][j], aw[3][j]);
        }
    }
    __syncthreads();

    float bv[SPT];
    int   bc[SPT];
    #pragma unroll
    for (int s = 0; s < SPT; s++) { bv[s] = __int_as_float(0xff800000); bc[s] = 0; }

    const ulonglong2* q = reinterpret_cast<const ulonglong2*>(tbl);
    #pragma unroll 2
    for (int c = 0; c < SPLIT_CAND; c++) {
        const ulonglong2 q0 = q[c * 5 + 0];   // dims 0,1 (each duplicated)
        const ulonglong2 q1 = q[c * 5 + 1];   // dims 2,3
        const ulonglong2 q2 = q[c * 5 + 2];   // dims 4,5
        const ulonglong2 q3 = q[c * 5 + 3];   // dims 6,7
        const ulonglong2 q4 = q[c * 5 + 4];   // dims 8,9

        unsigned long long a01 = fmul2(wd01[0], q0.x);
        unsigned long long a23 = fmul2(wd23[0], q0.x);
        a01 = ffma2(wd01[1], q0.y, a01);  a23 = ffma2(wd23[1], q0.y, a23);
        a01 = ffma2(wd01[2], q1.x, a01);  a23 = ffma2(wd23[2], q1.x, a23);
        a01 = ffma2(wd01[3], q1.y, a01);  a23 = ffma2(wd23[3], q1.y, a23);
        a01 = ffma2(wd01[4], q2.x, a01);  a23 = ffma2(wd23[4], q2.x, a23);
        a01 = ffma2(wd01[5], q2.y, a01);  a23 = ffma2(wd23[5], q2.y, a23);
        a01 = ffma2(wd01[6], q3.x, a01);  a23 = ffma2(wd23[6], q3.x, a23);
        a01 = ffma2(wd01[7], q3.y, a01);  a23 = ffma2(wd23[7], q3.y, a23);
        a01 = ffma2(wd01[8], q4.x, a01);  a23 = ffma2(wd23[8], q4.x, a23);
        a01 = ffma2(wd01[9], q4.y, a01);  a23 = ffma2(wd23[9], q4.y, a23);

        float d[SPT];
        unpack2(a01, d[0], d[1]);
        unpack2(a23, d[2], d[3]);
        #pragma unroll
        for (int s = 0; s < SPT; s++) {
            const bool gt = (d[s] > bv[s]);   // ascending c + strict '>' = first max
            bv[s] = gt ? d[s] : bv[s];
            bc[s] = gt ? c    : bc[s];
        }
    }

    #pragma unroll
    for (int s = 0; s < SPT; s++)
        g_pack[g[s]][split] = pack2(bv[s], __int_as_float(c0 + bc[s]));
}

// ---- merge: one contiguous 128B row per sample; splits ascend in index ----
__global__ void merge_kernel(float* __restrict__ out)
{
    const int i = blockIdx.x * 256 + threadIdx.x;
    const ulonglong2* row = reinterpret_cast<const ulonglong2*>(g_pack[i]);

    ulonglong2 r0 = row[0];
    float v, ixf;
    unpack2(r0.x, v, ixf);
    {
        float vs, ixs;
        unpack2(r0.y, vs, ixs);
        if (vs > v) { v = vs; ixf = ixs; }
    }
    #pragma unroll
    for (int h = 1; h < 6; h++) {            // splits 2..11
        const ulonglong2 r = row[h];
        float vs, ixs;
        unpack2(r.x, vs, ixs);
        if (vs > v) { v = vs; ixf = ixs; }
        unpack2(r.y, vs, ixs);
        if (vs > v) { v = vs; ixf = ixs; }
    }
    {
        const ulonglong2 r = row[6];          // split 12 (r.y is padding, skip)
        float vs, ixs;
        unpack2(r.x, vs, ixs);
        if (vs > v) { v = vs; ixf = ixs; }
    }
    out[i] = (float)(__float_as_int(ixf) + 1);
}

extern "C" void kernel_launch(void* const* d_in, const int* in_sizes, int n_in,
                              void* d_out, int out_size)
{
    // Order-proof binding: every float array has a unique element count.
    const void*  idA = nullptr;
    const void*  idB = nullptr;
    const float* worker_emb  = nullptr;  // 18070
    const float* project_emb = nullptr;  // 24900
    const float* W1 = nullptr;           // 800
    const float* b1 = nullptr;           // 40
    const float* W2 = nullptr;           // 400
    const float* b2 = nullptr;           // 10

    for (int i = 0; i < n_in; i++) {
        switch (in_sizes[i]) {
            case BATCH: if (!idA) idA = d_in[i];
                        else      idB = d_in[i];                      break;
            case 18070: worker_emb  = (const float*)d_in[i];          break;
            case 24900: project_emb = (const float*)d_in[i];          break;
            case 800:   W1 = (const float*)d_in[i];                   break;
            case 40:    b1 = (const float*)d_in[i];                   break;
            case 400:   W2 = (const float*)d_in[i];                   break;
            case 10:    b2 = (const float*)d_in[i];                   break;
            default: break;
        }
    }

    mlp_kernel<<<BATCH / THREADS, THREADS>>>(idA, idB, worker_emb, project_emb,
                                             W1, b1, W2, b2);
    actor_kernel<<<ACTOR_CTAS, THREADS>>>(project_emb);
    merge_kernel<<<BATCH / 256, 256>>>((float*)d_out);
}

// round 13
// speedup vs baseline: 1.0204x; 1.0204x over previous
#include <cuda_runtime.h>
#include <cuda_bf16.h>

// Problem constants
#define N_WORKER   1807
#define N_PROJECT  2490
#define EMB        10
#define STATE_DIM  20
#define HIDDEN     40
#define NCAND      2489        // candidates = project_emb rows 1..2489 (cand c -> row c+1)
#define BATCH      65536

#define NSPLIT     13
#define SPLIT_CAND 192         // 13*192 = 2496 >= 2489, NaN pad
#define THREADS    128
#define SPT        4           // samples per thread in actor
#define SBLK       (BATCH / (THREADS * SPT))   // 128 sample blocks
#define ACTOR_CTAS (SBLK * NSPLIT)             // 1664 CTAs @4/SM resident

#define W2T_PITCH  12          // padded transposed-W2 row (48B, 16-aligned)

// per-sample action weights (plain floats; actor packs sample-pairs)
__device__ float g_w[BATCH][EMB];
// per-split partial argmax: coalesced actor stores (R10 layout)
__device__ unsigned long long g_pack[NSPLIT][BATCH];

// ---- packed f32x2 helpers (sm_103a FFMA2 path) ----
__device__ __forceinline__ unsigned long long pack2(float lo, float hi) {
    unsigned long long r;
    asm("mov.b64 %0, {%1, %2};" : "=l"(r) : "f"(lo), "f"(hi));
    return r;
}
__device__ __forceinline__ void unpack2(unsigned long long v, float& lo, float& hi) {
    asm("mov.b64 {%0, %1}, %2;" : "=f"(lo), "=f"(hi) : "l"(v));
}
__device__ __forceinline__ unsigned long long fmul2(unsigned long long a, unsigned long long b) {
    unsigned long long d;
    asm("mul.rn.f32x2 %0, %1, %2;" : "=l"(d) : "l"(a), "l"(b));
    return d;
}
__device__ __forceinline__ unsigned long long ffma2(unsigned long long a, unsigned long long b,
                                                    unsigned long long c) {
    unsigned long long d;
    asm("fma.rn.f32x2 %0, %1, %2, %3;" : "=l"(d) : "l"(a), "l"(b), "l"(c));
    return d;
}

__device__ __forceinline__ int load_id(const void* p, int i, int ids64) {
    return ids64 ? (int)((const long long*)p)[i] : ((const int*)p)[i];
}

// ---- MLP kernel: 2 threads per sample (split over hidden units) ----
// Warp layout: lanes 0-15 = samples s0..s15 (hidden 0-19), lanes 16-31 = same
// samples (hidden 20-39). Partial action outputs combined via shfl_xor(16).
__global__ __launch_bounds__(THREADS)
void mlp_kernel(const void* __restrict__ idA,
                const void* __restrict__ idB,
                const float* __restrict__ worker_emb,
                const float* __restrict__ project_emb,
                const float* __restrict__ W1,
                const float* __restrict__ b1,
                const float* __restrict__ W2,
                const float* __restrict__ b2)
{
    __shared__ __align__(16) float sW1[HIDDEN * STATE_DIM];   // [k][j], 80B rows
    __shared__ __align__(16) float sW2t[HIDDEN * W2T_PITCH];  // [k][d], 48B rows
    __shared__ float sb1[HIDDEN];
    __shared__ float sb2[EMB];
    __shared__ unsigned int s_or[4], s_mx[4];
    __shared__ int s_swap, s_ids64;

    const int tid  = threadIdx.x;
    const int lane = tid & 31;

    // -- fused id-layout detection (128 sampled u64-slots; P[err] < e^-41) --
    {
        const unsigned int* a32 = (const unsigned int*)idA;
        const unsigned int* b32 = (const unsigned int*)idB;
        const int i = tid * (BATCH / 256);
        unsigned int odd_or  = a32[2 * i + 1] | b32[2 * i + 1];
        unsigned int even_mx = a32[2 * i];
        #pragma unroll
        for (int o = 16; o > 0; o >>= 1) {
            odd_or  |= __shfl_xor_sync(0xffffffffu, odd_or, o);
            even_mx  = max(even_mx, __shfl_xor_sync(0xffffffffu, even_mx, o));
        }
        if (lane == 0) { s_or[tid >> 5] = odd_or; s_mx[tid >> 5] = even_mx; }
    }

    for (int i = tid; i < HIDDEN * STATE_DIM; i += THREADS) sW1[i] = W1[i];
    for (int i = tid; i < HIDDEN * EMB; i += THREADS) {
        const int d = i / HIDDEN;
        const int k = i - d * HIDDEN;
        sW2t[k * W2T_PITCH + d] = W2[i];
    }
    if (tid < HIDDEN) sb1[tid] = b1[tid];
    if (tid < EMB)    sb2[tid] = b2[tid];
    __syncthreads();

    if (tid == 0) {
        unsigned int oo = 0, mm = 0;
        #pragma unroll
        for (int w = 0; w < 4; w++) { oo |= s_or[w]; mm = max(mm, s_mx[w]); }
        s_ids64 = (oo == 0) ? 1 : 0;
        s_swap  = (mm >= (unsigned)N_WORKER) ? 1 : 0;
    }
    __syncthreads();

    const int swap  = s_swap;
    const int ids64 = s_ids64;
    const void* worker_ids  = swap ? idB : idA;
    const void* project_ids = swap ? idA : idB;

    // sample index: 64 samples per CTA (16 per warp), half = lane>>4
    const int g    = blockIdx.x * 64 + (tid >> 5) * 16 + (lane & 15);
    const int half = lane >> 4;
    const int wi = load_id(worker_ids,  g, ids64);
    const int pi = load_id(project_ids, g, ids64);

    // vector gathers: row = 10 floats -> 5x float2 (8-aligned)
    float x[STATE_DIM];
    {
        const float2* wrow = reinterpret_cast<const float2*>(worker_emb + wi * EMB);
        const float2* prow = reinterpret_cast<const float2*>(project_emb + pi * EMB);
        #pragma unroll
        for (int j = 0; j < 5; j++) {
            const float2 a = __ldg(wrow + j);
            x[2 * j] = a.x; x[2 * j + 1] = a.y;
        }
        #pragma unroll
        for (int j = 0; j < 5; j++) {
            const float2 b = __ldg(prow + j);
            x[EMB + 2 * j] = b.x; x[EMB + 2 * j + 1] = b.y;
        }
    }

    float a[EMB];
    #pragma unroll
    for (int d = 0; d < EMB; d++) a[d] = half ? 0.0f : sb2[d];

    // this thread's 20 hidden units
    const int kbase = half * 20;
    #pragma unroll 2
    for (int ko = 0; ko < 20; ko += 2) {
        const int k0 = kbase + ko;
        const float4* r0 = reinterpret_cast<const float4*>(sW1 + k0 * STATE_DIM);
        const float4* r1 = reinterpret_cast<const float4*>(sW1 + (k0 + 1) * STATE_DIM);
        float h0 = sb1[k0], h1 = sb1[k0 + 1];
        #pragma unroll
        for (int q4 = 0; q4 < 5; q4++) {
            const float4 w0 = r0[q4];
            const float4 w1 = r1[q4];
            const int j = q4 * 4;
            h0 += w0.x * x[j] + w0.y * x[j + 1] + w0.z * x[j + 2] + w0.w * x[j + 3];
            h1 += w1.x * x[j] + w1.y * x[j + 1] + w1.z * x[j + 2] + w1.w * x[j + 3];
        }
        h0 = fmaxf(h0, 0.0f);
        h1 = fmaxf(h1, 0.0f);

        const float4* c0 = reinterpret_cast<const float4*>(sW2t + k0 * W2T_PITCH);
        const float4* c1 = reinterpret_cast<const float4*>(sW2t + (k0 + 1) * W2T_PITCH);
        const float4 u0 = c0[0], u1 = c0[1], u2 = c0[2];
        const float4 v0 = c1[0], v1 = c1[1], v2 = c1[2];
        a[0] += u0.x * h0 + v0.x * h1;
        a[1] += u0.y * h0 + v0.y * h1;
        a[2] += u0.z * h0 + v0.z * h1;
        a[3] += u0.w * h0 + v0.w * h1;
        a[4] += u1.x * h0 + v1.x * h1;
        a[5] += u1.y * h0 + v1.y * h1;
        a[6] += u1.z * h0 + v1.z * h1;
        a[7] += u1.w * h0 + v1.w * h1;
        a[8] += u2.x * h0 + v2.x * h1;
        a[9] += u2.y * h0 + v2.y * h1;
    }

    // combine halves: lane l <-> l+16 hold partial sums of the same sample
    #pragma unroll
    for (int d = 0; d < EMB; d++)
        a[d] += __shfl_xor_sync(0xffffffffu, a[d], 16);

    if (half == 0) {
        float2* wrow_out = reinterpret_cast<float2*>(g_w[g]);
        #pragma unroll
        for (int j = 0; j < 5; j++) wrow_out[j] = make_float2(a[2 * j], a[2 * j + 1]);
    }
}

// ---- actor: sample-pair packed dots; 4 samples/thread; 16 warps/SM ----
__global__ __launch_bounds__(THREADS, 4)
void actor_kernel(const float* __restrict__ project_emb)
{
    // duplicated-pair table: tbl[c*10 + j] = (t_c[j], t_c[j]); 15360 B
    __shared__ __align__(16) unsigned long long tbl[SPLIT_CAND * EMB];

    const int split = blockIdx.x % NSPLIT;
    const int sblk  = blockIdx.x / NSPLIT;
    const int c0    = split * SPLIT_CAND;     // global candidate base
    const int tid   = threadIdx.x;

    // stage duplicated pairs; NaN pad beyond NCAND (NaN never wins '>')
    for (int e = tid; e < SPLIT_CAND * EMB; e += THREADS) {
        const int c = e / EMB;
        const int j = e - c * EMB;
        const int ci = c0 + c;
        const float t = (ci < NCAND) ? __ldg(project_emb + (ci + 1) * EMB + j)
                                     : __int_as_float(0x7fffffff);
        tbl[e] = pack2(t, t);
    }

    // per-thread: 4 samples -> 2 sample-pair packed weight vectors (40 regs)
    int g[SPT];
    unsigned long long wd01[EMB], wd23[EMB];
    {
        float aw[SPT][EMB];
        #pragma unroll
        for (int s = 0; s < SPT; s++) {
            g[s] = (sblk * SPT + s) * THREADS + tid;
            const float2* wr = reinterpret_cast<const float2*>(g_w[g[s]]);
            #pragma unroll
            for (int j = 0; j < 5; j++) {
                const float2 v = __ldg(wr + j);
                aw[s][2 * j] = v.x; aw[s][2 * j + 1] = v.y;
            }
        }
        #pragma unroll
        for (int j = 0; j < EMB; j++) {
            wd01[j] = pack2(aw[0][j], aw[1][j]);
            wd23[j] = pack2(aw[2][j], aw[3][j]);
        }
    }
    __syncthreads();

    float bv[SPT];
    int   bc[SPT];
    #pragma unroll
    for (int s = 0; s < SPT; s++) { bv[s] = __int_as_float(0xff800000); bc[s] = 0; }

    const ulonglong2* q = reinterpret_cast<const ulonglong2*>(tbl);
    #pragma unroll 2
    for (int c = 0; c < SPLIT_CAND; c++) {
        const ulonglong2 q0 = q[c * 5 + 0];   // dims 0,1 (each duplicated)
        const ulonglong2 q1 = q[c * 5 + 1];   // dims 2,3
        const ulonglong2 q2 = q[c * 5 + 2];   // dims 4,5
        const ulonglong2 q3 = q[c * 5 + 3];   // dims 6,7
        const ulonglong2 q4 = q[c * 5 + 4];   // dims 8,9

        unsigned long long a01 = fmul2(wd01[0], q0.x);
        unsigned long long a23 = fmul2(wd23[0], q0.x);
        a01 = ffma2(wd01[1], q0.y, a01);  a23 = ffma2(wd23[1], q0.y, a23);
        a01 = ffma2(wd01[2], q1.x, a01);  a23 = ffma2(wd23[2], q1.x, a23);
        a01 = ffma2(wd01[3], q1.y, a01);  a23 = ffma2(wd23[3], q1.y, a23);
        a01 = ffma2(wd01[4], q2.x, a01);  a23 = ffma2(wd23[4], q2.x, a23);
        a01 = ffma2(wd01[5], q2.y, a01);  a23 = ffma2(wd23[5], q2.y, a23);
        a01 = ffma2(wd01[6], q3.x, a01);  a23 = ffma2(wd23[6], q3.x, a23);
        a01 = ffma2(wd01[7], q3.y, a01);  a23 = ffma2(wd23[7], q3.y, a23);
        a01 = ffma2(wd01[8], q4.x, a01);  a23 = ffma2(wd23[8], q4.x, a23);
        a01 = ffma2(wd01[9], q4.y, a01);  a23 = ffma2(wd23[9], q4.y, a23);

        float d[SPT];
        unpack2(a01, d[0], d[1]);
        unpack2(a23, d[2], d[3]);
        #pragma unroll
        for (int s = 0; s < SPT; s++) {
            const bool gt = (d[s] > bv[s]);   // ascending c + strict '>' = first max
            bv[s] = gt ? d[s] : bv[s];
            bc[s] = gt ? c    : bc[s];
        }
    }

    #pragma unroll
    for (int s = 0; s < SPT; s++)
        g_pack[split][g[s]] = pack2(bv[s], __int_as_float(c0 + bc[s]));
}

// ---- merge the 13 splits; splits ascend in index: strict '>' keeps first max ----
__global__ void merge_kernel(float* __restrict__ out)
{
    const int i = blockIdx.x * 256 + threadIdx.x;
    float v, ixf;
    unpack2(g_pack[0][i], v, ixf);
    #pragma unroll
    for (int s = 1; s < NSPLIT; s++) {
        float vs, ixs;
        unpack2(g_pack[s][i], vs, ixs);
        const bool t = (vs > v);
        v   = t ? vs  : v;
        ixf = t ? ixs : ixf;
    }
    out[i] = (float)(__float_as_int(ixf) + 1);
}

extern "C" void kernel_launch(void* const* d_in, const int* in_sizes, int n_in,
                              void* d_out, int out_size)
{
    // Order-proof binding: every float array has a unique element count.
    const void*  idA = nullptr;
    const void*  idB = nullptr;
    const float* worker_emb  = nullptr;  // 18070
    const float* project_emb = nullptr;  // 24900
    const float* W1 = nullptr;           // 800
    const float* b1 = nullptr;           // 40
    const float* W2 = nullptr;           // 400
    const float* b2 = nullptr;           // 10

    for (int i = 0; i < n_in; i++) {
        switch (in_sizes[i]) {
            case BATCH: if (!idA) idA = d_in[i];
                        else      idB = d_in[i];                      break;
            case 18070: worker_emb  = (const float*)d_in[i];          break;
            case 24900: project_emb = (const float*)d_in[i];          break;
            case 800:   W1 = (const float*)d_in[i];                   break;
            case 40:    b1 = (const float*)d_in[i];                   break;
            case 400:   W2 = (const float*)d_in[i];                   break;
            case 10:    b2 = (const float*)d_in[i];                   break;
            default: break;
        }
    }

    mlp_kernel<<<BATCH / 64, THREADS>>>(idA, idB, worker_emb, project_emb,
                                        W1, b1, W2, b2);
    actor_kernel<<<ACTOR_CTAS, THREADS>>>(project_emb);
    merge_kernel<<<BATCH / 256, 256>>>((float*)d_out);
}

// round 14
// speedup vs baseline: 1.0250x; 1.0046x over previous
#include <cuda_runtime.h>
#include <cuda_bf16.h>

// Problem constants
#define N_WORKER   1807
#define N_PROJECT  2490
#define EMB        10
#define STATE_DIM  20
#define HIDDEN     40
#define NCAND      2489        // candidates = project_emb rows 1..2489 (cand c -> row c+1)
#define BATCH      65536

#define NSPLIT     13
#define SPLIT_CAND 192         // 13*192 = 2496 >= 2489; overflow slots clamp to cand 2488
#define THREADS    128
#define SPT        4           // samples per thread in actor
#define SBLK       (BATCH / (THREADS * SPT))   // 128 sample blocks
#define ACTOR_CTAS (SBLK * NSPLIT)             // 1664 CTAs @4/SM resident

#define W2T_PITCH  12          // padded transposed-W2 row (48B, 16-aligned)

// per-sample action weights (plain floats; actor packs sample-pairs)
__device__ float g_w[BATCH][EMB];
// per-sample global argmax accumulator: (ord(val) << 32) | (NCAND - idx)
__device__ unsigned long long g_best[BATCH];

// ---- packed f32x2 helpers (sm_103a FFMA2 path) ----
__device__ __forceinline__ unsigned long long pack2(float lo, float hi) {
    unsigned long long r;
    asm("mov.b64 %0, {%1, %2};" : "=l"(r) : "f"(lo), "f"(hi));
    return r;
}
__device__ __forceinline__ void unpack2(unsigned long long v, float& lo, float& hi) {
    asm("mov.b64 {%0, %1}, %2;" : "=f"(lo), "=f"(hi) : "l"(v));
}
__device__ __forceinline__ unsigned long long fmul2(unsigned long long a, unsigned long long b) {
    unsigned long long d;
    asm("mul.rn.f32x2 %0, %1, %2;" : "=l"(d) : "l"(a), "l"(b));
    return d;
}
__device__ __forceinline__ unsigned long long ffma2(unsigned long long a, unsigned long long b,
                                                    unsigned long long c) {
    unsigned long long d;
    asm("fma.rn.f32x2 %0, %1, %2, %3;" : "=l"(d) : "l"(a), "l"(b), "l"(c));
    return d;
}

// order-preserving float->u32: f1 > f2  <=>  ord(f1) > ord(f2)  (finite floats)
__device__ __forceinline__ unsigned int ord_encode(float f) {
    unsigned int b = __float_as_uint(f);
    return ((int)b < 0) ? ~b : (b | 0x80000000u);
}

__device__ __forceinline__ int load_id(const void* p, int i, int ids64) {
    return ids64 ? (int)((const long long*)p)[i] : ((const int*)p)[i];
}

// ---- MLP kernel: 2 threads per sample (split over hidden units) ----
// lanes 0-15 = samples (hidden 0-19, loads worker row), lanes 16-31 = same
// samples (hidden 20-39, loads project row). x exchanged via shfl_xor(16).
__global__ __launch_bounds__(THREADS)
void mlp_kernel(const void* __restrict__ idA,
                const void* __restrict__ idB,
                const float* __restrict__ worker_emb,
                const float* __restrict__ project_emb,
                const float* __restrict__ W1,
                const float* __restrict__ b1,
                const float* __restrict__ W2,
                const float* __restrict__ b2)
{
    __shared__ __align__(16) float sW1[HIDDEN * STATE_DIM];   // [k][j], 80B rows
    __shared__ __align__(16) float sW2t[HIDDEN * W2T_PITCH];  // [k][d], 48B rows
    __shared__ float sb1[HIDDEN];
    __shared__ float sb2[EMB];
    __shared__ unsigned int s_or[4], s_mx[4];
    __shared__ int s_swap, s_ids64;

    const int tid  = threadIdx.x;
    const int lane = tid & 31;

    // -- fused id-layout detection (128 sampled u64-slots; P[err] < e^-41) --
    {
        const unsigned int* a32 = (const unsigned int*)idA;
        const unsigned int* b32 = (const unsigned int*)idB;
        const int i = tid * (BATCH / 256);
        unsigned int odd_or  = a32[2 * i + 1] | b32[2 * i + 1];
        unsigned int even_mx = a32[2 * i];
        #pragma unroll
        for (int o = 16; o > 0; o >>= 1) {
            odd_or  |= __shfl_xor_sync(0xffffffffu, odd_or, o);
            even_mx  = max(even_mx, __shfl_xor_sync(0xffffffffu, even_mx, o));
        }
        if (lane == 0) { s_or[tid >> 5] = odd_or; s_mx[tid >> 5] = even_mx; }
    }

    for (int i = tid; i < HIDDEN * STATE_DIM; i += THREADS) sW1[i] = W1[i];
    for (int i = tid; i < HIDDEN * EMB; i += THREADS) {
        const int d = i / HIDDEN;
        const int k = i - d * HIDDEN;
        sW2t[k * W2T_PITCH + d] = W2[i];
    }
    if (tid < HIDDEN) sb1[tid] = b1[tid];
    if (tid < EMB)    sb2[tid] = b2[tid];
    __syncthreads();

    if (tid == 0) {
        unsigned int oo = 0, mm = 0;
        #pragma unroll
        for (int w = 0; w < 4; w++) { oo |= s_or[w]; mm = max(mm, s_mx[w]); }
        s_ids64 = (oo == 0) ? 1 : 0;
        s_swap  = (mm >= (unsigned)N_WORKER) ? 1 : 0;
    }
    __syncthreads();

    const int swap  = s_swap;
    const int ids64 = s_ids64;
    const void* worker_ids  = swap ? idB : idA;
    const void* project_ids = swap ? idA : idB;

    // 64 samples per CTA (16 per warp); half = lane>>4
    const int g    = blockIdx.x * 64 + (tid >> 5) * 16 + (lane & 15);
    const int half = lane >> 4;

    // split gather: half0 loads worker row, half1 loads project row (5 LDG.64)
    float mine[EMB];
    {
        const int id = half ? load_id(project_ids, g, ids64)
                            : load_id(worker_ids,  g, ids64);
        const float2* row = half
            ? reinterpret_cast<const float2*>(project_emb + id * EMB)
            : reinterpret_cast<const float2*>(worker_emb + id * EMB);
        #pragma unroll
        for (int j = 0; j < 5; j++) {
            const float2 v = __ldg(row + j);
            mine[2 * j] = v.x; mine[2 * j + 1] = v.y;
        }
    }
    // exchange: build full x[20] = [worker | project]
    float x[STATE_DIM];
    #pragma unroll
    for (int j = 0; j < EMB; j++) {
        const float other = __shfl_xor_sync(0xffffffffu, mine[j], 16);
        x[j]       = half ? other   : mine[j];   // worker part
        x[EMB + j] = half ? mine[j] : other;     // project part
    }

    float a[EMB];
    #pragma unroll
    for (int d = 0; d < EMB; d++) a[d] = half ? 0.0f : sb2[d];

    // this thread's 20 hidden units
    const int kbase = half * 20;
    #pragma unroll 2
    for (int ko = 0; ko < 20; ko += 2) {
        const int k0 = kbase + ko;
        const float4* r0 = reinterpret_cast<const float4*>(sW1 + k0 * STATE_DIM);
        const float4* r1 = reinterpret_cast<const float4*>(sW1 + (k0 + 1) * STATE_DIM);
        float h0 = sb1[k0], h1 = sb1[k0 + 1];
        #pragma unroll
        for (int q4 = 0; q4 < 5; q4++) {
            const float4 w0 = r0[q4];
            const float4 w1 = r1[q4];
            const int j = q4 * 4;
            h0 += w0.x * x[j] + w0.y * x[j + 1] + w0.z * x[j + 2] + w0.w * x[j + 3];
            h1 += w1.x * x[j] + w1.y * x[j + 1] + w1.z * x[j + 2] + w1.w * x[j + 3];
        }
        h0 = fmaxf(h0, 0.0f);
        h1 = fmaxf(h1, 0.0f);

        const float4* c0 = reinterpret_cast<const float4*>(sW2t + k0 * W2T_PITCH);
        const float4* c1 = reinterpret_cast<const float4*>(sW2t + (k0 + 1) * W2T_PITCH);
        const float4 u0 = c0[0], u1 = c0[1], u2 = c0[2];
        const float4 v0 = c1[0], v1 = c1[1], v2 = c1[2];
        a[0] += u0.x * h0 + v0.x * h1;
        a[1] += u0.y * h0 + v0.y * h1;
        a[2] += u0.z * h0 + v0.z * h1;
        a[3] += u0.w * h0 + v0.w * h1;
        a[4] += u1.x * h0 + v1.x * h1;
        a[5] += u1.y * h0 + v1.y * h1;
        a[6] += u1.z * h0 + v1.z * h1;
        a[7] += u1.w * h0 + v1.w * h1;
        a[8] += u2.x * h0 + v2.x * h1;
        a[9] += u2.y * h0 + v2.y * h1;
    }

    // combine halves (lane l <-> l+16 hold partials of the same sample)
    #pragma unroll
    for (int d = 0; d < EMB; d++)
        a[d] += __shfl_xor_sync(0xffffffffu, a[d], 16);

    if (half == 0) {
        float2* wrow_out = reinterpret_cast<float2*>(g_w[g]);
        #pragma unroll
        for (int j = 0; j < 5; j++) wrow_out[j] = make_float2(a[2 * j], a[2 * j + 1]);
    } else {
        g_best[g] = 0ULL;   // init for actor's atomicMax (every packed value > 0)
    }
}

// ---- actor: sample-pair packed dots; atomicMax merge epilogue ----
__global__ __launch_bounds__(THREADS, 4)
void actor_kernel(const float* __restrict__ project_emb)
{
    // duplicated-pair table: tbl[c*10 + j] = (t_c[j], t_c[j]); 15360 B
    __shared__ __align__(16) unsigned long long tbl[SPLIT_CAND * EMB];

    const int split = blockIdx.x % NSPLIT;
    const int sblk  = blockIdx.x / NSPLIT;
    const int c0    = split * SPLIT_CAND;     // global candidate base
    const int tid   = threadIdx.x;

    // stage duplicated pairs; overflow slots CLAMP to candidate NCAND-1
    // (duplicates are exact; strict '>' in ascending order keeps the first = real slot)
    for (int e = tid; e < SPLIT_CAND * EMB; e += THREADS) {
        const int c = e / EMB;
        const int j = e - c * EMB;
        const int ci = min(c0 + c, NCAND - 1);
        const float t = __ldg(project_emb + (ci + 1) * EMB + j);
        tbl[e] = pack2(t, t);
    }

    // per-thread: 4 samples -> 2 sample-pair packed weight vectors (40 regs)
    int g[SPT];
    unsigned long long wd01[EMB], wd23[EMB];
    {
        float aw[SPT][EMB];
        #pragma unroll
        for (int s = 0; s < SPT; s++) {
            g[s] = (sblk * SPT + s) * THREADS + tid;
            const float2* wr = reinterpret_cast<const float2*>(g_w[g[s]]);
            #pragma unroll
            for (int j = 0; j < 5; j++) {
                const float2 v = __ldg(wr + j);
                aw[s][2 * j] = v.x; aw[s][2 * j + 1] = v.y;
            }
        }
        #pragma unroll
        for (int j = 0; j < EMB; j++) {
            wd01[j] = pack2(aw[0][j], aw[1][j]);
            wd23[j] = pack2(aw[2][j], aw[3][j]);
        }
    }
    __syncthreads();

    float bv[SPT];
    int   bc[SPT];
    #pragma unroll
    for (int s = 0; s < SPT; s++) { bv[s] = __int_as_float(0xff800000); bc[s] = 0; }

    const ulonglong2* q = reinterpret_cast<const ulonglong2*>(tbl);
    #pragma unroll 2
    for (int c = 0; c < SPLIT_CAND; c++) {
        const ulonglong2 q0 = q[c * 5 + 0];   // dims 0,1 (each duplicated)
        const ulonglong2 q1 = q[c * 5 + 1];   // dims 2,3
        const ulonglong2 q2 = q[c * 5 + 2];   // dims 4,5
        const ulonglong2 q3 = q[c * 5 + 3];   // dims 6,7
        const ulonglong2 q4 = q[c * 5 + 4];   // dims 8,9

        unsigned long long a01 = fmul2(wd01[0], q0.x);
        unsigned long long a23 = fmul2(wd23[0], q0.x);
        a01 = ffma2(wd01[1], q0.y, a01);  a23 = ffma2(wd23[1], q0.y, a23);
        a01 = ffma2(wd01[2], q1.x, a01);  a23 = ffma2(wd23[2], q1.x, a23);
        a01 = ffma2(wd01[3], q1.y, a01);  a23 = ffma2(wd23[3], q1.y, a23);
        a01 = ffma2(wd01[4], q2.x, a01);  a23 = ffma2(wd23[4], q2.x, a23);
        a01 = ffma2(wd01[5], q2.y, a01);  a23 = ffma2(wd23[5], q2.y, a23);
        a01 = ffma2(wd01[6], q3.x, a01);  a23 = ffma2(wd23[6], q3.x, a23);
        a01 = ffma2(wd01[7], q3.y, a01);  a23 = ffma2(wd23[7], q3.y, a23);
        a01 = ffma2(wd01[8], q4.x, a01);  a23 = ffma2(wd23[8], q4.x, a23);
        a01 = ffma2(wd01[9], q4.y, a01);  a23 = ffma2(wd23[9], q4.y, a23);

        float d[SPT];
        unpack2(a01, d[0], d[1]);
        unpack2(a23, d[2], d[3]);
        #pragma unroll
        for (int s = 0; s < SPT; s++) {
            const bool gt = (d[s] > bv[s]);   // ascending c + strict '>' = first max
            bv[s] = gt ? d[s] : bv[s];
            bc[s] = gt ? c    : bc[s];
        }
    }

    // atomic merge: larger val wins; on equal val, larger (NCAND-idx) = smaller idx wins
    #pragma unroll
    for (int s = 0; s < SPT; s++) {
        const int gidx = min(c0 + bc[s], NCAND - 1);
        const unsigned long long packed =
            ((unsigned long long)ord_encode(bv[s]) << 32) |
            (unsigned int)(NCAND - gidx);
        atomicMax(&g_best[g[s]], packed);
    }
}

// ---- decode: packed best -> float index ----
__global__ void out_kernel(float* __restrict__ out)
{
    const int i = blockIdx.x * 256 + threadIdx.x;
    const unsigned long long p = g_best[i];
    const int idx = NCAND - (int)(p & 0xffffffffu);
    out[i] = (float)(idx + 1);
}

extern "C" void kernel_launch(void* const* d_in, const int* in_sizes, int n_in,
                              void* d_out, int out_size)
{
    // Order-proof binding: every float array has a unique element count.
    const void*  idA = nullptr;
    const void*  idB = nullptr;
    const float* worker_emb  = nullptr;  // 18070
    const float* project_emb = nullptr;  // 24900
    const float* W1 = nullptr;           // 800
    const float* b1 = nullptr;           // 40
    const float* W2 = nullptr;           // 400
    const float* b2 = nullptr;           // 10

    for (int i = 0; i < n_in; i++) {
        switch (in_sizes[i]) {
            case BATCH: if (!idA) idA = d_in[i];
                        else      idB = d_in[i];                      break;
            case 18070: worker_emb  = (const float*)d_in[i];          break;
            case 24900: project_emb = (const float*)d_in[i];          break;
            case 800:   W1 = (const float*)d_in[i];                   break;
            case 40:    b1 = (const float*)d_in[i];                   break;
            case 400:   W2 = (const float*)d_in[i];                   break;
            case 10:    b2 = (const float*)d_in[i];                   break;
            default: break;
        }
    }

    mlp_kernel<<<BATCH / 64, THREADS>>>(idA, idB, worker_emb, project_emb,
                                        W1, b1, W2, b2);
    actor_kernel<<<ACTOR_CTAS, THREADS>>>(project_emb);
    out_kernel<<<BATCH / 256, 256>>>((float*)d_out);
}